// round 16
// baseline (speedup 1.0000x reference)
#include <cuda_runtime.h>
#include <cuda_bf16.h>
#include <cstdint>

#define NN 50000
#define NE 1600000
#define NF 1433
#define NH 256
#define NC 7
#define NFP 1440                 // NF padded to 16*90
#define MP  50048                // NN padded to 128*391
#define NT_K (NFP / 16)          // 90
#define SCAN_NB 196              // 196*256 = 50176 >= NN

// ------------------- scratch (static device globals; no runtime alloc) ----
__device__ int   g_cnt[NN];
__device__ int   g_rowptr[NN + 1];
__device__ int   g_cur[NN];
__device__ float g_dinv[NN];
__device__ int   g_col[NE];
__device__ int   g_is64;
__device__ int   g_part[SCAN_NB];
__device__ __nv_bfloat16 g_xh[(size_t)MP * NFP];   // hi(x)  [node][k], zero-padded
__device__ __nv_bfloat16 g_xl[(size_t)MP * NFP];   // lo(x)
__device__ __nv_bfloat16 g_wh[(size_t)NFP * NH];   // hi(W1) [k][n], zero-padded
__device__ __nv_bfloat16 g_wl[(size_t)NFP * NH];   // lo(W1)
__device__ float g_h [(size_t)NN * NH];   // x @ W1
__device__ float g_h1[(size_t)NN * NH];   // relu(agg1 + b1)
__device__ float g_g [NN * 8];            // h1 @ W2, padded stride 8

// ------------------- mma/ldmatrix/cp.async helpers (sm_80 baseline ISA) ----
__device__ __forceinline__ uint32_t smem_u32(const void* p) {
    uint32_t a;
    asm("{ .reg .u64 t; cvta.to.shared.u64 t, %1; cvt.u32.u64 %0, t; }"
        : "=r"(a) : "l"(p));
    return a;
}
__device__ __forceinline__ void ldsm_x4(uint32_t* r, uint32_t a) {
    asm volatile("ldmatrix.sync.aligned.m8n8.x4.shared.b16 {%0,%1,%2,%3}, [%4];"
                 : "=r"(r[0]), "=r"(r[1]), "=r"(r[2]), "=r"(r[3]) : "r"(a));
}
__device__ __forceinline__ void ldsm_x4_t(uint32_t* r, uint32_t a) {
    asm volatile("ldmatrix.sync.aligned.m8n8.x4.trans.shared.b16 {%0,%1,%2,%3}, [%4];"
                 : "=r"(r[0]), "=r"(r[1]), "=r"(r[2]), "=r"(r[3]) : "r"(a));
}
__device__ __forceinline__ void mma16816(float* d, const uint32_t* a, const uint32_t* b) {
    asm volatile("mma.sync.aligned.m16n8k16.row.col.f32.bf16.bf16.f32 "
                 "{%0,%1,%2,%3}, {%4,%5,%6,%7}, {%8,%9}, {%0,%1,%2,%3};"
                 : "+f"(d[0]), "+f"(d[1]), "+f"(d[2]), "+f"(d[3])
                 : "r"(a[0]), "r"(a[1]), "r"(a[2]), "r"(a[3]), "r"(b[0]), "r"(b[1]));
}
__device__ __forceinline__ void cp16(uint32_t dst, const void* src) {
    asm volatile("cp.async.ca.shared.global [%0], [%1], 16;"
                 :: "r"(dst), "l"(src) : "memory");
}
#define CP_COMMIT() asm volatile("cp.async.commit_group;" ::: "memory")
#define CP_WAIT1()  asm volatile("cp.async.wait_group 1;" ::: "memory")

// ------------------- dtype detection ---------------------------------------
__global__ void detect_kernel(const int* __restrict__ ei32) {
    if (threadIdx.x == 0 && blockIdx.x == 0) {
        int flag = 1;
        for (int i = 1; i < 200; i += 2)
            if (ei32[i] != 0) { flag = 0; break; }
        g_is64 = flag;
    }
}
__device__ __forceinline__ int edge_src(const int* ei32, int e) {
    return g_is64 ? ei32[2 * (size_t)e] : ei32[e];
}
__device__ __forceinline__ int edge_dst(const int* ei32, int e) {
    return g_is64 ? ei32[2 * ((size_t)NE + e)] : ei32[NE + e];
}

// ------------------- bf16 hi/lo split (once, streaming) ---------------------
__global__ void split_x_kernel(const float* __restrict__ x) {
    size_t idx = (size_t)blockIdx.x * 256 + threadIdx.x;   // one 8-col chunk
    if (idx >= (size_t)MP * NFP / 8) return;
    size_t base = idx * 8;
    int row = (int)(base / NFP);
    int col = (int)(base % NFP);
    __align__(16) __nv_bfloat16 hv[8], lv[8];
    #pragma unroll
    for (int j = 0; j < 8; j++) {
        int c = col + j;
        float v = (row < NN && c < NF) ? x[(size_t)row * NF + c] : 0.f;
        __nv_bfloat16 hb = __float2bfloat16(v);
        hv[j] = hb;
        lv[j] = __float2bfloat16(v - __bfloat162float(hb));
    }
    *(uint4*)&g_xh[base] = *(const uint4*)hv;
    *(uint4*)&g_xl[base] = *(const uint4*)lv;
}
__global__ void split_w_kernel(const float* __restrict__ W1) {
    int idx = blockIdx.x * 256 + threadIdx.x;   // [k][n], k-major
    if (idx >= NFP * NH) return;
    int k = idx >> 8;
    int n = idx & 255;
    float v = (k < NF) ? W1[(size_t)k * NH + n] : 0.f;
    __nv_bfloat16 hb = __float2bfloat16(v);
    g_wh[idx] = hb;
    g_wl[idx] = __float2bfloat16(v - __bfloat162float(hb));
}

// ------------------- graph preprocessing ------------------------------------
__global__ void zero_cnt_kernel() {
    int i = blockIdx.x * blockDim.x + threadIdx.x;
    if (i < NN) g_cnt[i] = 0;
}
__global__ void count_kernel(const int* __restrict__ ei32) {
    int e = blockIdx.x * blockDim.x + threadIdx.x;
    if (e < NE) {
        int d = edge_dst(ei32, e);
        if ((unsigned)d < NN) atomicAdd(&g_cnt[d], 1);
    }
}

// ---- parallel scan: A) block sums, B) scan partials, C) per-block prefix ---
__device__ __forceinline__ int block_excl_scan_256(int v, int tid, int* warp_sums,
                                                   int* total_out) {
    const int lane = tid & 31, wid = tid >> 5;
    int x = v;
    #pragma unroll
    for (int o = 1; o < 32; o <<= 1) {
        int t = __shfl_up_sync(0xffffffffu, x, o);
        if (lane >= o) x += t;
    }
    if (lane == 31) warp_sums[wid] = x;
    __syncthreads();
    if (tid < 8) {
        int y = warp_sums[tid];
        #pragma unroll
        for (int o = 1; o < 8; o <<= 1) {
            int t = __shfl_up_sync(0xffu, y, o);
            if (tid >= o) y += t;
        }
        warp_sums[tid] = y;
    }
    __syncthreads();
    int excl = x - v + (wid ? warp_sums[wid - 1] : 0);
    *total_out = warp_sums[7];
    return excl;
}

__global__ void scanA_kernel() {       // 196 blocks x 256: per-block sums
    __shared__ int warp_sums[8];
    const int tid = threadIdx.x;
    int i = blockIdx.x * 256 + tid;
    int v = (i < NN) ? g_cnt[i] : 0;
    int lane = tid & 31, wid = tid >> 5;
    int x = v;
    #pragma unroll
    for (int o = 1; o < 32; o <<= 1) x += __shfl_down_sync(0xffffffffu, x, o);
    if (lane == 0) warp_sums[wid] = x;
    __syncthreads();
    if (tid == 0) {
        int s = 0;
        #pragma unroll
        for (int w = 0; w < 8; w++) s += warp_sums[w];
        g_part[blockIdx.x] = s;
    }
}
__global__ void scanB_kernel() {       // 1 block x 256: exclusive scan partials
    __shared__ int warp_sums[8];
    const int tid = threadIdx.x;
    int v = (tid < SCAN_NB) ? g_part[tid] : 0;
    int total;
    int excl = block_excl_scan_256(v, tid, warp_sums, &total);
    if (tid < SCAN_NB) g_part[tid] = excl;
    if (tid == 0) g_rowptr[NN] = total;
}
__global__ void scanC_kernel() {       // 196 blocks x 256: write prefixes
    __shared__ int warp_sums[8];
    const int tid = threadIdx.x;
    int i = blockIdx.x * 256 + tid;
    int v = (i < NN) ? g_cnt[i] : 0;
    int total;
    int excl = block_excl_scan_256(v, tid, warp_sums, &total) + g_part[blockIdx.x];
    if (i < NN) {
        g_rowptr[i] = excl;
        g_cur[i]    = excl;
        g_dinv[i]   = rsqrtf((float)(v + 1));   // +1 = self loop
    }
}

__global__ void fill_kernel(const int* __restrict__ ei32) {
    int e = blockIdx.x * blockDim.x + threadIdx.x;
    if (e < NE) {
        int s = edge_src(ei32, e);
        int d = edge_dst(ei32, e);
        if ((unsigned)s < NN && (unsigned)d < NN) {
            int p = atomicAdd(&g_cur[d], 1);
            if ((unsigned)p < NE) g_col[p] = s;
        }
    }
}

// ------------------- GEMM1: g_h = x @ W1 via HMMA bf16 3-pass ---------------
// CTA tile 128x128, 8 warps (warp = 32m x 64n), K-step 16.
// cp.async 3-stage pipeline on pre-split bf16 planes: compute warps run
// only LDSM+HMMA; 4 cp.async.16B per thread per stage; 1 barrier per k-step.
#define ST_AH 0
#define ST_AL 6144
#define ST_BH 12288
#define ST_BL 16640
#define ST_SZ 20992
#define NSTAGE 3
#define SMEM_GEMM (NSTAGE * ST_SZ)

__global__ void __launch_bounds__(256, 2) mma_gemm1_kernel() {
    extern __shared__ __align__(16) char smem[];
    const uint32_t sb = smem_u32(smem);
    const int tid  = threadIdx.x;
    const int lane = tid & 31, wid = tid >> 5;
    const int row0 = blockIdx.y * 128;
    const int col0 = blockIdx.x * 128;
    const int wm = wid & 3;
    const int wn = wid >> 2;

    float acc[2][8][4];
    #pragma unroll
    for (int i = 0; i < 2; i++)
        #pragma unroll
        for (int j = 0; j < 8; j++)
            #pragma unroll
            for (int r = 0; r < 4; r++) acc[i][j][r] = 0.f;

    // cp.async thread roles (256 threads cover each plane exactly once)
    const int ar = tid >> 1, ac = tid & 1;      // A: 128 rows x 2 chunks (32B/row)
    const int br = tid >> 4, bc = tid & 15;     // B: 16 rows x 16 chunks (256B/row)
    const size_t a_goff = (size_t)(row0 + ar) * NFP + ac * 8;
    const size_t b_goff = (size_t)br * NH + col0 + bc * 8;
    const uint32_t a_soff = ar * 48 + ac * 16;
    const uint32_t b_soff = br * 272 + bc * 16;

    // fill stage s with k-tile kt
    #define FILL_STAGE(s, kt)                                                  \
        do {                                                                   \
            uint32_t st_ = sb + (uint32_t)(s) * ST_SZ;                         \
            cp16(st_ + ST_AH + a_soff, g_xh + a_goff + (size_t)(kt) * 16);     \
            cp16(st_ + ST_AL + a_soff, g_xl + a_goff + (size_t)(kt) * 16);     \
            cp16(st_ + ST_BH + b_soff, g_wh + b_goff + (size_t)(kt) * 16 * NH);\
            cp16(st_ + ST_BL + b_soff, g_wl + b_goff + (size_t)(kt) * 16 * NH);\
        } while (0)

    FILL_STAGE(0, 0); CP_COMMIT();
    FILL_STAGE(1, 1); CP_COMMIT();

    const uint32_t a_lrow = (lane & 15);
    const uint32_t a_lcb  = (uint32_t)(lane >> 4) << 4;
    const uint32_t b_lk   = (lane & 7) + ((lane & 8) ? 8 : 0);
    const uint32_t b_ln   = (lane & 16) ? 8 : 0;
    const uint32_t arow   = (uint32_t)(wm * 32 + a_lrow) * 48 + a_lcb;

    int buf = 0;
    for (int t = 0; t < NT_K; t++) {
        CP_WAIT1();            // stage t resident (<=1 group outstanding)
        __syncthreads();       // visible to all warps

        if (t + 2 < NT_K) {
            int nb = buf + 2; if (nb >= NSTAGE) nb -= NSTAGE;
            FILL_STAGE(nb, t + 2);
        }
        CP_COMMIT();           // empty groups keep the wait-count invariant

        // ---- compute on stage buf: acc += Ah*Bh + Al*Bh + Ah*Bl ----------
        {
            const uint32_t base = sb + (uint32_t)buf * ST_SZ;
            uint32_t ah0[4], ah1[4], al0[4], al1[4];
            ldsm_x4(ah0, base + ST_AH + arow);
            ldsm_x4(ah1, base + ST_AH + arow + 16 * 48);
            ldsm_x4(al0, base + ST_AL + arow);
            ldsm_x4(al1, base + ST_AL + arow + 16 * 48);
            #pragma unroll
            for (int jj = 0; jj < 4; jj++) {
                const uint32_t boff = b_lk * 272 +
                                      (uint32_t)(wn * 64 + jj * 16 + b_ln) * 2;
                uint32_t bh[4];
                ldsm_x4_t(bh, base + ST_BH + boff);
                mma16816(acc[0][2 * jj],     ah0, bh);
                mma16816(acc[0][2 * jj + 1], ah0, bh + 2);
                mma16816(acc[1][2 * jj],     ah1, bh);
                mma16816(acc[1][2 * jj + 1], ah1, bh + 2);
                mma16816(acc[0][2 * jj],     al0, bh);
                mma16816(acc[0][2 * jj + 1], al0, bh + 2);
                mma16816(acc[1][2 * jj],     al1, bh);
                mma16816(acc[1][2 * jj + 1], al1, bh + 2);
                uint32_t bl[4];
                ldsm_x4_t(bl, base + ST_BL + boff);
                mma16816(acc[0][2 * jj],     ah0, bl);
                mma16816(acc[0][2 * jj + 1], ah0, bl + 2);
                mma16816(acc[1][2 * jj],     ah1, bl);
                mma16816(acc[1][2 * jj + 1], ah1, bl + 2);
            }
        }
        if (++buf == NSTAGE) buf = 0;
    }
    #undef FILL_STAGE

    #pragma unroll
    for (int i = 0; i < 2; i++) {
        int row = row0 + wm * 32 + i * 16 + (lane >> 2);
        #pragma unroll
        for (int j = 0; j < 8; j++) {
            int colb = col0 + wn * 64 + j * 8 + (lane & 3) * 2;
            if (row < NN)
                *(float2*)&g_h[(size_t)row * NH + colb] =
                    make_float2(acc[i][j][0], acc[i][j][1]);
            if (row + 8 < NN)
                *(float2*)&g_h[(size_t)(row + 8) * NH + colb] =
                    make_float2(acc[i][j][2], acc[i][j][3]);
        }
    }
}

// ------------------- aggregation layer 1 (CSR gather, no atomics) -----------
__global__ void agg1_kernel(const float* __restrict__ b1) {
    __shared__ int   scol[128];
    __shared__ float snrm[128];
    const int i = blockIdx.x;
    const int f = threadIdx.x;   // 256 = NH
    const int start = g_rowptr[i];
    const int end   = g_rowptr[i + 1];
    float acc = 0.f;
    for (int p0 = start; p0 < end; p0 += 128) {
        int n = min(128, end - p0);
        if (f < n) {
            int s = g_col[p0 + f];
            scol[f] = s;
            snrm[f] = g_dinv[s];
        }
        __syncthreads();
        int j = 0;
        for (; j + 4 <= n; j += 4) {
            int s0 = scol[j], s1 = scol[j + 1], s2 = scol[j + 2], s3 = scol[j + 3];
            float w0 = snrm[j], w1 = snrm[j + 1], w2 = snrm[j + 2], w3 = snrm[j + 3];
            float h0  = g_h[(size_t)s0 * NH + f];
            float h1v = g_h[(size_t)s1 * NH + f];
            float h2  = g_h[(size_t)s2 * NH + f];
            float h3  = g_h[(size_t)s3 * NH + f];
            acc = fmaf(w0, h0, acc);
            acc = fmaf(w1, h1v, acc);
            acc = fmaf(w2, h2, acc);
            acc = fmaf(w3, h3, acc);
        }
        for (; j < n; j++)
            acc = fmaf(snrm[j], g_h[(size_t)scol[j] * NH + f], acc);
        __syncthreads();
    }
    float di = g_dinv[i];
    float v  = fmaf(di, acc, di * di * g_h[(size_t)i * NH + f]) + b1[f];
    g_h1[(size_t)i * NH + f] = fmaxf(v, 0.f);
}

// ------------------- GEMM2: g_g = h1[NN,256] @ W2[256,7] --------------------
__global__ void gemm2_kernel(const float* __restrict__ W2) {
    __shared__ float sW[NH * NC];
    const int tid = threadIdx.x;
    for (int t = tid; t < NH * NC; t += 256) sW[t] = W2[t];
    __syncthreads();
    const int lane = tid & 31;
    const int node = blockIdx.x * 8 + (tid >> 5);
    float p[NC];
    #pragma unroll
    for (int j = 0; j < NC; j++) p[j] = 0.f;
    #pragma unroll
    for (int u = 0; u < 8; u++) {
        int k = u * 32 + lane;
        float v = g_h1[(size_t)node * NH + k];
        #pragma unroll
        for (int j = 0; j < NC; j++) p[j] = fmaf(v, sW[k * NC + j], p[j]);
    }
    #pragma unroll
    for (int o = 16; o > 0; o >>= 1)
        #pragma unroll
        for (int j = 0; j < NC; j++) p[j] += __shfl_down_sync(0xffffffffu, p[j], o);
    if (lane == 0) {
        #pragma unroll
        for (int j = 0; j < NC; j++) g_g[node * 8 + j] = p[j];
        g_g[node * 8 + 7] = 0.f;
    }
}

// ------------------- aggregation layer 2 (7-wide, CSR gather) ---------------
__global__ void agg2_kernel(const float* __restrict__ b2, float* __restrict__ out) {
    const int tid  = threadIdx.x;
    const int node = blockIdx.x * 32 + (tid >> 3);
    const int j    = tid & 7;
    if (node >= NN) return;
    const int start = g_rowptr[node], end = g_rowptr[node + 1];
    float acc = 0.f;
    for (int p = start; p < end; p++) {
        int s = g_col[p];
        acc = fmaf(g_dinv[s], g_g[s * 8 + j], acc);
    }
    float di = g_dinv[node];
    float v  = fmaf(di, acc, di * di * g_g[node * 8 + j]);
    if (j < NC) out[node * NC + j] = v + b2[j];
}

// ------------------- launch --------------------------------------------------
extern "C" void kernel_launch(void* const* d_in, const int* in_sizes, int n_in,
                              void* d_out, int out_size) {
    const float* x    = (const float*)d_in[0];
    const int*   ei32 = (const int*)d_in[1];   // int32 OR int64 (auto-detected)
    const float* W1   = (const float*)d_in[2];
    const float* b1   = (const float*)d_in[3];
    const float* W2   = (const float*)d_in[4];
    const float* b2   = (const float*)d_in[5];
    float*       out  = (float*)d_out;

    cudaFuncSetAttribute(mma_gemm1_kernel,
                         cudaFuncAttributeMaxDynamicSharedMemorySize, SMEM_GEMM);

    detect_kernel<<<1, 32>>>(ei32);
    {
        size_t chunks = (size_t)MP * NFP / 8;
        split_x_kernel<<<(unsigned)((chunks + 255) / 256), 256>>>(x);
    }
    split_w_kernel<<<(NFP * NH + 255) / 256, 256>>>(W1);

    // gemm1 placed 4th so the ncu capture window (-s 5 -c 1) lands on it.
    dim3 g1(2, MP / 128);   // (n-tiles, m-tiles) = (2, 391)
    mma_gemm1_kernel<<<g1, 256, SMEM_GEMM>>>();

    zero_cnt_kernel<<<(NN + 255) / 256, 256>>>();
    count_kernel<<<(NE + 255) / 256, 256>>>(ei32);
    scanA_kernel<<<SCAN_NB, 256>>>();
    scanB_kernel<<<1, 256>>>();
    scanC_kernel<<<SCAN_NB, 256>>>();
    fill_kernel<<<(NE + 255) / 256, 256>>>(ei32);

    agg1_kernel<<<NN, 256>>>(b1);
    gemm2_kernel<<<NN / 8, 256>>>(W2);
    agg2_kernel<<<(NN + 31) / 32, 256>>>(b2, out);
}

// round 17
// speedup vs baseline: 1.0046x; 1.0046x over previous
#include <cuda_runtime.h>
#include <cuda_bf16.h>
#include <cstdint>

#define NN 50000
#define NE 1600000
#define NF 1433
#define NH 256
#define NC 7
#define NFP 1440                 // NF padded to 16*90
#define MP  50048                // NN padded to 128*391
#define NT32 (NFP / 32)          // 45 k-steps of 32
#define SCAN_NB 196              // 196*256 = 50176 >= NN

// ------------------- scratch (static device globals; no runtime alloc) ----
__device__ int   g_cnt[NN];
__device__ int   g_rowptr[NN + 1];
__device__ int   g_cur[NN];
__device__ float g_dinv[NN];
__device__ int   g_col[NE];
__device__ int   g_is64;
__device__ int   g_part[SCAN_NB];
__device__ __nv_bfloat16 g_xh[(size_t)MP * NFP];   // hi(x)  [node][k], zero-padded
__device__ __nv_bfloat16 g_xl[(size_t)MP * NFP];   // lo(x)
__device__ __nv_bfloat16 g_wh[(size_t)NFP * NH];   // hi(W1) [k][n], zero-padded
__device__ __nv_bfloat16 g_wl[(size_t)NFP * NH];   // lo(W1)
__device__ float g_h [(size_t)NN * NH];   // x @ W1
__device__ float g_h1[(size_t)NN * NH];   // relu(agg1 + b1)
__device__ float g_g [NN * 8];            // h1 @ W2, padded stride 8

// ------------------- mma/ldmatrix/cp.async helpers (sm_80 baseline ISA) ----
__device__ __forceinline__ uint32_t smem_u32(const void* p) {
    uint32_t a;
    asm("{ .reg .u64 t; cvta.to.shared.u64 t, %1; cvt.u32.u64 %0, t; }"
        : "=r"(a) : "l"(p));
    return a;
}
__device__ __forceinline__ void ldsm_x4(uint32_t* r, uint32_t a) {
    asm volatile("ldmatrix.sync.aligned.m8n8.x4.shared.b16 {%0,%1,%2,%3}, [%4];"
                 : "=r"(r[0]), "=r"(r[1]), "=r"(r[2]), "=r"(r[3]) : "r"(a));
}
__device__ __forceinline__ void ldsm_x4_t(uint32_t* r, uint32_t a) {
    asm volatile("ldmatrix.sync.aligned.m8n8.x4.trans.shared.b16 {%0,%1,%2,%3}, [%4];"
                 : "=r"(r[0]), "=r"(r[1]), "=r"(r[2]), "=r"(r[3]) : "r"(a));
}
__device__ __forceinline__ void mma16816(float* d, const uint32_t* a, const uint32_t* b) {
    asm volatile("mma.sync.aligned.m16n8k16.row.col.f32.bf16.bf16.f32 "
                 "{%0,%1,%2,%3}, {%4,%5,%6,%7}, {%8,%9}, {%0,%1,%2,%3};"
                 : "+f"(d[0]), "+f"(d[1]), "+f"(d[2]), "+f"(d[3])
                 : "r"(a[0]), "r"(a[1]), "r"(a[2]), "r"(a[3]), "r"(b[0]), "r"(b[1]));
}
__device__ __forceinline__ void cp16(uint32_t dst, const void* src) {
    asm volatile("cp.async.ca.shared.global [%0], [%1], 16;"
                 :: "r"(dst), "l"(src) : "memory");
}
#define CP_COMMIT() asm volatile("cp.async.commit_group;" ::: "memory")
#define CP_WAIT0()  asm volatile("cp.async.wait_group 0;" ::: "memory")

// ------------------- dtype detection ---------------------------------------
__global__ void detect_kernel(const int* __restrict__ ei32) {
    if (threadIdx.x == 0 && blockIdx.x == 0) {
        int flag = 1;
        for (int i = 1; i < 200; i += 2)
            if (ei32[i] != 0) { flag = 0; break; }
        g_is64 = flag;
    }
}
__device__ __forceinline__ int edge_src(const int* ei32, int e) {
    return g_is64 ? ei32[2 * (size_t)e] : ei32[e];
}
__device__ __forceinline__ int edge_dst(const int* ei32, int e) {
    return g_is64 ? ei32[2 * ((size_t)NE + e)] : ei32[NE + e];
}

// ------------------- bf16 hi/lo split (once, streaming) ---------------------
__global__ void split_x_kernel(const float* __restrict__ x) {
    size_t idx = (size_t)blockIdx.x * 256 + threadIdx.x;   // one 8-col chunk
    if (idx >= (size_t)MP * NFP / 8) return;
    size_t base = idx * 8;
    int row = (int)(base / NFP);
    int col = (int)(base % NFP);
    __align__(16) __nv_bfloat16 hv[8], lv[8];
    #pragma unroll
    for (int j = 0; j < 8; j++) {
        int c = col + j;
        float v = (row < NN && c < NF) ? x[(size_t)row * NF + c] : 0.f;
        __nv_bfloat16 hb = __float2bfloat16(v);
        hv[j] = hb;
        lv[j] = __float2bfloat16(v - __bfloat162float(hb));
    }
    *(uint4*)&g_xh[base] = *(const uint4*)hv;
    *(uint4*)&g_xl[base] = *(const uint4*)lv;
}
__global__ void split_w_kernel(const float* __restrict__ W1) {
    int idx = blockIdx.x * 256 + threadIdx.x;   // [k][n], k-major
    if (idx >= NFP * NH) return;
    int k = idx >> 8;
    int n = idx & 255;
    float v = (k < NF) ? W1[(size_t)k * NH + n] : 0.f;
    __nv_bfloat16 hb = __float2bfloat16(v);
    g_wh[idx] = hb;
    g_wl[idx] = __float2bfloat16(v - __bfloat162float(hb));
}

// ------------------- graph preprocessing ------------------------------------
__global__ void zero_cnt_kernel() {
    int i = blockIdx.x * blockDim.x + threadIdx.x;
    if (i < NN) g_cnt[i] = 0;
}
__global__ void count_kernel(const int* __restrict__ ei32) {
    int e = blockIdx.x * blockDim.x + threadIdx.x;
    if (e < NE) {
        int d = edge_dst(ei32, e);
        if ((unsigned)d < NN) atomicAdd(&g_cnt[d], 1);
    }
}

// ---- parallel scan: A) block sums, B) scan partials, C) per-block prefix ---
__device__ __forceinline__ int block_excl_scan_256(int v, int tid, int* warp_sums,
                                                   int* total_out) {
    const int lane = tid & 31, wid = tid >> 5;
    int x = v;
    #pragma unroll
    for (int o = 1; o < 32; o <<= 1) {
        int t = __shfl_up_sync(0xffffffffu, x, o);
        if (lane >= o) x += t;
    }
    if (lane == 31) warp_sums[wid] = x;
    __syncthreads();
    if (tid < 8) {
        int y = warp_sums[tid];
        #pragma unroll
        for (int o = 1; o < 8; o <<= 1) {
            int t = __shfl_up_sync(0xffu, y, o);
            if (tid >= o) y += t;
        }
        warp_sums[tid] = y;
    }
    __syncthreads();
    int excl = x - v + (wid ? warp_sums[wid - 1] : 0);
    *total_out = warp_sums[7];
    return excl;
}

__global__ void scanA_kernel() {       // 196 blocks x 256: per-block sums
    __shared__ int warp_sums[8];
    const int tid = threadIdx.x;
    int i = blockIdx.x * 256 + tid;
    int v = (i < NN) ? g_cnt[i] : 0;
    int lane = tid & 31, wid = tid >> 5;
    int x = v;
    #pragma unroll
    for (int o = 1; o < 32; o <<= 1) x += __shfl_down_sync(0xffffffffu, x, o);
    if (lane == 0) warp_sums[wid] = x;
    __syncthreads();
    if (tid == 0) {
        int s = 0;
        #pragma unroll
        for (int w = 0; w < 8; w++) s += warp_sums[w];
        g_part[blockIdx.x] = s;
    }
}
__global__ void scanB_kernel() {       // 1 block x 256: exclusive scan partials
    __shared__ int warp_sums[8];
    const int tid = threadIdx.x;
    int v = (tid < SCAN_NB) ? g_part[tid] : 0;
    int total;
    int excl = block_excl_scan_256(v, tid, warp_sums, &total);
    if (tid < SCAN_NB) g_part[tid] = excl;
    if (tid == 0) g_rowptr[NN] = total;
}
__global__ void scanC_kernel() {       // 196 blocks x 256: write prefixes
    __shared__ int warp_sums[8];
    const int tid = threadIdx.x;
    int i = blockIdx.x * 256 + tid;
    int v = (i < NN) ? g_cnt[i] : 0;
    int total;
    int excl = block_excl_scan_256(v, tid, warp_sums, &total) + g_part[blockIdx.x];
    if (i < NN) {
        g_rowptr[i] = excl;
        g_cur[i]    = excl;
        g_dinv[i]   = rsqrtf((float)(v + 1));   // +1 = self loop
    }
}

__global__ void fill_kernel(const int* __restrict__ ei32) {
    int e = blockIdx.x * blockDim.x + threadIdx.x;
    if (e < NE) {
        int s = edge_src(ei32, e);
        int d = edge_dst(ei32, e);
        if ((unsigned)s < NN && (unsigned)d < NN) {
            int p = atomicAdd(&g_cur[d], 1);
            if ((unsigned)p < NE) g_col[p] = s;
        }
    }
}

// ------------------- GEMM1: g_h = x @ W1 via HMMA bf16 3-pass ---------------
// CTA tile 128x128, 8 warps (warp = 32m x 64n), K-step 32 (2 x 16 sub-slices),
// cp.async double-buffer on pre-split bf16 planes. 45 barriers (was 90).
#define SUB_A 6144               // one A plane sub-slice: 128 rows x 48B pitch
#define SUB_B 4352               // one B plane sub-slice: 16 k x 272B pitch
#define OFF_AH 0
#define OFF_AL 12288
#define OFF_BH 24576
#define OFF_BL 33280
#define ST_SZ  41984
#define NSTAGE 2
#define SMEM_GEMM (NSTAGE * ST_SZ)

__global__ void __launch_bounds__(256, 2) mma_gemm1_kernel() {
    extern __shared__ __align__(16) char smem[];
    const uint32_t sb = smem_u32(smem);
    const int tid  = threadIdx.x;
    const int lane = tid & 31, wid = tid >> 5;
    const int row0 = blockIdx.y * 128;
    const int col0 = blockIdx.x * 128;
    const int wm = wid & 3;
    const int wn = wid >> 2;

    float acc[2][8][4];
    #pragma unroll
    for (int i = 0; i < 2; i++)
        #pragma unroll
        for (int j = 0; j < 8; j++)
            #pragma unroll
            for (int r = 0; r < 4; r++) acc[i][j][r] = 0.f;

    // cp.async thread roles (256 threads cover each plane sub-slice once)
    const int ar = tid >> 1, ac = tid & 1;      // A: 128 rows x 2 chunks (32B/row)
    const int br = tid >> 4, bc = tid & 15;     // B: 16 k x 16 chunks (256B/row)
    const size_t a_goff = (size_t)(row0 + ar) * NFP + ac * 8;
    const size_t b_goff = (size_t)br * NH + col0 + bc * 8;
    const uint32_t a_soff = ar * 48 + ac * 16;
    const uint32_t b_soff = br * 272 + bc * 16;

    // fill stage s with 32-k tile kt32 (sub-slices 2*kt32, 2*kt32+1)
    #define FILL_STAGE(s, kt32)                                                   \
        do {                                                                      \
            uint32_t st_ = sb + (uint32_t)(s) * ST_SZ;                            \
            _Pragma("unroll")                                                     \
            for (int sub_ = 0; sub_ < 2; sub_++) {                                \
                int kt_ = (kt32) * 2 + sub_;                                      \
                cp16(st_ + OFF_AH + sub_ * SUB_A + a_soff,                        \
                     g_xh + a_goff + (size_t)kt_ * 16);                           \
                cp16(st_ + OFF_AL + sub_ * SUB_A + a_soff,                        \
                     g_xl + a_goff + (size_t)kt_ * 16);                           \
                cp16(st_ + OFF_BH + sub_ * SUB_B + b_soff,                        \
                     g_wh + b_goff + (size_t)kt_ * 16 * NH);                      \
                cp16(st_ + OFF_BL + sub_ * SUB_B + b_soff,                        \
                     g_wl + b_goff + (size_t)kt_ * 16 * NH);                      \
            }                                                                     \
        } while (0)

    FILL_STAGE(0, 0); CP_COMMIT();

    const uint32_t a_lrow = (lane & 15);
    const uint32_t a_lcb  = (uint32_t)(lane >> 4) << 4;
    const uint32_t b_lk   = (lane & 7) + ((lane & 8) ? 8 : 0);
    const uint32_t b_ln   = (lane & 16) ? 8 : 0;
    const uint32_t arow   = (uint32_t)(wm * 32 + a_lrow) * 48 + a_lcb;

    for (int t = 0; t < NT32; t++) {
        const int buf = t & 1;
        CP_WAIT0();            // stage t resident
        __syncthreads();       // all warps past stage t-1 compute; visible

        if (t + 1 < NT32) {
            FILL_STAGE(buf ^ 1, t + 1);
            CP_COMMIT();
        }

        // ---- compute both 16-k sub-slices: acc += Ah*Bh + Al*Bh + Ah*Bl ---
        const uint32_t base = sb + (uint32_t)buf * ST_SZ;
        #pragma unroll
        for (int sub = 0; sub < 2; sub++) {
            const uint32_t abase = base + sub * SUB_A;
            const uint32_t bbase = base + sub * SUB_B;
            uint32_t ah0[4], ah1[4], al0[4], al1[4];
            ldsm_x4(ah0, abase + OFF_AH + arow);
            ldsm_x4(ah1, abase + OFF_AH + arow + 16 * 48);
            ldsm_x4(al0, abase + OFF_AL + arow);
            ldsm_x4(al1, abase + OFF_AL + arow + 16 * 48);
            #pragma unroll
            for (int jj = 0; jj < 4; jj++) {
                const uint32_t boff = b_lk * 272 +
                                      (uint32_t)(wn * 64 + jj * 16 + b_ln) * 2;
                uint32_t bh[4];
                ldsm_x4_t(bh, bbase + OFF_BH + boff);
                mma16816(acc[0][2 * jj],     ah0, bh);
                mma16816(acc[0][2 * jj + 1], ah0, bh + 2);
                mma16816(acc[1][2 * jj],     ah1, bh);
                mma16816(acc[1][2 * jj + 1], ah1, bh + 2);
                mma16816(acc[0][2 * jj],     al0, bh);
                mma16816(acc[0][2 * jj + 1], al0, bh + 2);
                mma16816(acc[1][2 * jj],     al1, bh);
                mma16816(acc[1][2 * jj + 1], al1, bh + 2);
                uint32_t bl[4];
                ldsm_x4_t(bl, bbase + OFF_BL + boff);
                mma16816(acc[0][2 * jj],     ah0, bl);
                mma16816(acc[0][2 * jj + 1], ah0, bl + 2);
                mma16816(acc[1][2 * jj],     ah1, bl);
                mma16816(acc[1][2 * jj + 1], ah1, bl + 2);
            }
        }
    }
    #undef FILL_STAGE

    #pragma unroll
    for (int i = 0; i < 2; i++) {
        int row = row0 + wm * 32 + i * 16 + (lane >> 2);
        #pragma unroll
        for (int j = 0; j < 8; j++) {
            int colb = col0 + wn * 64 + j * 8 + (lane & 3) * 2;
            if (row < NN)
                *(float2*)&g_h[(size_t)row * NH + colb] =
                    make_float2(acc[i][j][0], acc[i][j][1]);
            if (row + 8 < NN)
                *(float2*)&g_h[(size_t)(row + 8) * NH + colb] =
                    make_float2(acc[i][j][2], acc[i][j][3]);
        }
    }
}

// ------------------- aggregation layer 1 (CSR gather, no atomics) -----------
__global__ void agg1_kernel(const float* __restrict__ b1) {
    __shared__ int   scol[128];
    __shared__ float snrm[128];
    const int i = blockIdx.x;
    const int f = threadIdx.x;   // 256 = NH
    const int start = g_rowptr[i];
    const int end   = g_rowptr[i + 1];
    float acc = 0.f;
    for (int p0 = start; p0 < end; p0 += 128) {
        int n = min(128, end - p0);
        if (f < n) {
            int s = g_col[p0 + f];
            scol[f] = s;
            snrm[f] = g_dinv[s];
        }
        __syncthreads();
        int j = 0;
        for (; j + 4 <= n; j += 4) {
            int s0 = scol[j], s1 = scol[j + 1], s2 = scol[j + 2], s3 = scol[j + 3];
            float w0 = snrm[j], w1 = snrm[j + 1], w2 = snrm[j + 2], w3 = snrm[j + 3];
            float h0  = g_h[(size_t)s0 * NH + f];
            float h1v = g_h[(size_t)s1 * NH + f];
            float h2  = g_h[(size_t)s2 * NH + f];
            float h3  = g_h[(size_t)s3 * NH + f];
            acc = fmaf(w0, h0, acc);
            acc = fmaf(w1, h1v, acc);
            acc = fmaf(w2, h2, acc);
            acc = fmaf(w3, h3, acc);
        }
        for (; j < n; j++)
            acc = fmaf(snrm[j], g_h[(size_t)scol[j] * NH + f], acc);
        __syncthreads();
    }
    float di = g_dinv[i];
    float v  = fmaf(di, acc, di * di * g_h[(size_t)i * NH + f]) + b1[f];
    g_h1[(size_t)i * NH + f] = fmaxf(v, 0.f);
}

// ------------------- GEMM2: g_g = h1[NN,256] @ W2[256,7] --------------------
__global__ void gemm2_kernel(const float* __restrict__ W2) {
    __shared__ float sW[NH * NC];
    const int tid = threadIdx.x;
    for (int t = tid; t < NH * NC; t += 256) sW[t] = W2[t];
    __syncthreads();
    const int lane = tid & 31;
    const int node = blockIdx.x * 8 + (tid >> 5);
    float p[NC];
    #pragma unroll
    for (int j = 0; j < NC; j++) p[j] = 0.f;
    #pragma unroll
    for (int u = 0; u < 8; u++) {
        int k = u * 32 + lane;
        float v = g_h1[(size_t)node * NH + k];
        #pragma unroll
        for (int j = 0; j < NC; j++) p[j] = fmaf(v, sW[k * NC + j], p[j]);
    }
    #pragma unroll
    for (int o = 16; o > 0; o >>= 1)
        #pragma unroll
        for (int j = 0; j < NC; j++) p[j] += __shfl_down_sync(0xffffffffu, p[j], o);
    if (lane == 0) {
        #pragma unroll
        for (int j = 0; j < NC; j++) g_g[node * 8 + j] = p[j];
        g_g[node * 8 + 7] = 0.f;
    }
}

// ------------------- aggregation layer 2 (7-wide, CSR gather) ---------------
__global__ void agg2_kernel(const float* __restrict__ b2, float* __restrict__ out) {
    const int tid  = threadIdx.x;
    const int node = blockIdx.x * 32 + (tid >> 3);
    const int j    = tid & 7;
    if (node >= NN) return;
    const int start = g_rowptr[node], end = g_rowptr[node + 1];
    float acc = 0.f;
    for (int p = start; p < end; p++) {
        int s = g_col[p];
        acc = fmaf(g_dinv[s], g_g[s * 8 + j], acc);
    }
    float di = g_dinv[node];
    float v  = fmaf(di, acc, di * di * g_g[node * 8 + j]);
    if (j < NC) out[node * NC + j] = v + b2[j];
}

// ------------------- launch --------------------------------------------------
extern "C" void kernel_launch(void* const* d_in, const int* in_sizes, int n_in,
                              void* d_out, int out_size) {
    const float* x    = (const float*)d_in[0];
    const int*   ei32 = (const int*)d_in[1];   // int32 OR int64 (auto-detected)
    const float* W1   = (const float*)d_in[2];
    const float* b1   = (const float*)d_in[3];
    const float* W2   = (const float*)d_in[4];
    const float* b2   = (const float*)d_in[5];
    float*       out  = (float*)d_out;

    // persistent side stream + fork/join events (host objects; created once,
    // before the harness's capture call; no device memory involved)
    static cudaStream_t s2 = 0;
    static cudaEvent_t  ev_root = 0, ev_join = 0;
    static int stream_ok = -1;
    if (stream_ok < 0) {
        stream_ok = (cudaStreamCreateWithFlags(&s2, cudaStreamNonBlocking) == cudaSuccess &&
                     cudaEventCreateWithFlags(&ev_root, cudaEventDisableTiming) == cudaSuccess &&
                     cudaEventCreateWithFlags(&ev_join, cudaEventDisableTiming) == cudaSuccess)
                    ? 1 : 0;
        cudaFuncSetAttribute(mma_gemm1_kernel,
                             cudaFuncAttributeMaxDynamicSharedMemorySize, SMEM_GEMM);
    }
    cudaStream_t sp = stream_ok ? s2 : 0;   // preprocessing stream (fallback: serial)

    if (stream_ok) {
        cudaEventRecord(ev_root, 0);
        cudaStreamWaitEvent(sp, ev_root, 0);
    }

    // ---- branch B (preprocessing) on side stream ----
    detect_kernel<<<1, 32, 0, sp>>>(ei32);
    zero_cnt_kernel<<<(NN + 255) / 256, 256, 0, sp>>>();
    count_kernel<<<(NE + 255) / 256, 256, 0, sp>>>(ei32);
    scanA_kernel<<<SCAN_NB, 256, 0, sp>>>();
    scanB_kernel<<<1, 256, 0, sp>>>();
    scanC_kernel<<<SCAN_NB, 256, 0, sp>>>();
    fill_kernel<<<(NE + 255) / 256, 256, 0, sp>>>(ei32);
    if (stream_ok) cudaEventRecord(ev_join, sp);

    // ---- branch A (splits + gemm1) on main stream ----
    {
        size_t chunks = (size_t)MP * NFP / 8;
        split_x_kernel<<<(unsigned)((chunks + 255) / 256), 256>>>(x);
    }
    split_w_kernel<<<(NFP * NH + 255) / 256, 256>>>(W1);
    dim3 g1(2, MP / 128);   // (n-tiles, m-tiles) = (2, 391)
    mma_gemm1_kernel<<<g1, 256, SMEM_GEMM>>>();

    // ---- join, then the dependent tail ----
    if (stream_ok) cudaStreamWaitEvent(0, ev_join, 0);
    agg1_kernel<<<NN, 256>>>(b1);
    gemm2_kernel<<<NN / 8, 256>>>(W2);
    agg2_kernel<<<(NN + 31) / 32, 256>>>(b2, out);
}